// round 10
// baseline (speedup 1.0000x reference)
#include <cuda_runtime.h>
#include <cuda_fp16.h>
#include <math.h>

#define NNODES 100000
#define KNB 16

// Scratch (bss, no allocation). h reused by both layers (sequential stream).
__device__ __align__(16) __half g_h[NNODES * 64];
__device__ __align__(16) float  g_x1[NNODES * 64];
__device__ float g_sd[NNODES];
__device__ float g_ss[NNODES];

// ---- helpers ---------------------------------------------------------------
__device__ __forceinline__ unsigned cvt_tf32(float f) {
    unsigned u;
    asm("cvt.rna.tf32.f32 %0, %1;" : "=r"(u) : "f"(f));
    return u;
}
__device__ __forceinline__ void mma_tf32(float* c,
    unsigned a0, unsigned a1, unsigned a2, unsigned a3,
    unsigned b0, unsigned b1)
{
    asm volatile(
        "mma.sync.aligned.m16n8k8.row.col.f32.tf32.tf32.f32 "
        "{%0,%1,%2,%3}, {%4,%5,%6,%7}, {%8,%9}, {%0,%1,%2,%3};"
        : "+f"(c[0]), "+f"(c[1]), "+f"(c[2]), "+f"(c[3])
        : "r"(a0), "r"(a1), "r"(a2), "r"(a3), "r"(b0), "r"(b1));
}
__device__ __forceinline__ unsigned smem_u32(const void* p) {
    unsigned a;
    asm("{ .reg .u64 t; cvta.to.shared.u64 t, %1; cvt.u32.u64 %0, t; }"
        : "=r"(a) : "l"(p));
    return a;
}
__device__ __forceinline__ void cp_async16(unsigned dst, const void* src, int sz) {
    asm volatile("cp.async.ca.shared.global [%0], [%1], 16, %2;"
                 :: "r"(dst), "l"(src), "r"(sz));
}
__device__ __forceinline__ unsigned long long pack2s(float lo, float hi) {
    unsigned long long r;
    asm("mov.b64 %0, {%1, %2};" : "=l"(r) : "f"(lo), "f"(hi));
    return r;
}
__device__ __forceinline__ unsigned long long pack2(float v) {
    unsigned long long r;
    asm("mov.b64 %0, {%1, %1};" : "=l"(r) : "f"(v));
    return r;
}
__device__ __forceinline__ void ffma2(unsigned long long& d,
                                      unsigned long long a,
                                      unsigned long long b) {
    asm("fma.rn.f32x2 %0, %1, %2, %0;" : "+l"(d) : "l"(a), "l"(b));
}
__device__ __forceinline__ float2 unpack2(unsigned long long v) {
    float2 f;
    asm("mov.b64 {%0, %1}, %2;" : "=f"(f.x), "=f"(f.y) : "l"(v));
    return f;
}

// ---------------------------------------------------------------------------
// GEMM h = x @ W (KD inner, 64 cols) on tf32 tensor cores + fused attention
// dots sd[i]=h[i].a[0:64], ss[i]=h[i].a[64:128]; h stored fp16.
// x tile cp.async'd as RAW fp32 bits (tensor core truncates to tf32); the
// -3.52e-4 truncation bias is cancelled by scaling W (rna) at fill time.
// ---------------------------------------------------------------------------
template <int KD>
__global__ void __launch_bounds__(256) gemm_mma_kernel(
    const float* __restrict__ x, const float* __restrict__ W,
    const float* __restrict__ a, __half* __restrict__ h,
    float* __restrict__ sd, float* __restrict__ ss)
{
    constexpr int XS = KD + 4;   // padded x row stride (u32 units)
    constexpr int WS = 72;       // padded W row stride (u32 units)
    extern __shared__ unsigned smem_u[];
    unsigned* Wsu = smem_u;               // KD x WS   (tf32-rna, bias-comp)
    unsigned* xsu = smem_u + KD * WS;     // 128 x XS  (raw fp32 bits)

    const int tid  = threadIdx.x;
    const int warp = tid >> 5;
    const int lane = tid & 31;
    const int q = lane & 3;
    const int g = lane >> 2;
    const int rowbase = blockIdx.x * 128;

    // x tile: raw-bit async copy with zero-fill past the last valid row
    {
        constexpr int K4 = KD / 4;
        const float4* xg = reinterpret_cast<const float4*>(x + (size_t)rowbase * KD);
        const unsigned xsa = smem_u32(xsu);
        const int tot = 128 * K4;
        const int nvr = NNODES - rowbase;
        const int validv = (nvr >= 128) ? tot : nvr * K4;
        for (int i = tid; i < tot; i += 256) {
            const int r = i / K4, k4 = i % K4;
            const unsigned dst = xsa + (unsigned)(r * XS + k4 * 4) * 4u;
            const int sz = (i < validv) ? 16 : 0;
            cp_async16(dst, xg + (sz ? i : 0), sz);
        }
        asm volatile("cp.async.commit_group;");
    }
    // W tile: rna cvt + truncation-bias compensation (tiny: KD*64 elements)
    {
        const float comp = 1.000352f;
        const float4* Wg = reinterpret_cast<const float4*>(W);
        #pragma unroll
        for (int i = tid; i < KD * 16; i += 256) {
            const float4 v = Wg[i];
            const int k = i >> 4, n4 = i & 15;
            uint4 u;
            u.x = cvt_tf32(v.x * comp); u.y = cvt_tf32(v.y * comp);
            u.z = cvt_tf32(v.z * comp); u.w = cvt_tf32(v.w * comp);
            *reinterpret_cast<uint4*>(&Wsu[k * WS + n4 * 4]) = u;
        }
    }
    asm volatile("cp.async.wait_group 0;");
    __syncthreads();

    float acc[8][4];
    #pragma unroll
    for (int nt = 0; nt < 8; nt++)
        #pragma unroll
        for (int j = 0; j < 4; j++) acc[nt][j] = 0.0f;

    const unsigned* xw = &xsu[(warp * 16) * XS];

    #pragma unroll
    for (int k0 = 0; k0 < KD; k0 += 8) {
        const unsigned a0 = xw[g * XS + k0 + q];
        const unsigned a1 = xw[(g + 8) * XS + k0 + q];
        const unsigned a2 = xw[g * XS + k0 + q + 4];
        const unsigned a3 = xw[(g + 8) * XS + k0 + q + 4];
        #pragma unroll
        for (int nt = 0; nt < 8; nt++) {
            const unsigned b0 = Wsu[(k0 + q) * WS + nt * 8 + g];
            const unsigned b1 = Wsu[(k0 + q + 4) * WS + nt * 8 + g];
            mma_tf32(acc[nt], a0, a1, a2, a3, b0, b1);
        }
    }

    // Fused attention dots. Thread owns rows (16w+g, 16w+g+8), cols {8nt+2q,+1}.
    float pd0 = 0.f, ps0 = 0.f, pd1 = 0.f, ps1 = 0.f;
    #pragma unroll
    for (int nt = 0; nt < 8; nt++) {
        const float2 av = reinterpret_cast<const float2*>(a)[nt * 4 + q];
        const float2 bv = reinterpret_cast<const float2*>(a + 64)[nt * 4 + q];
        pd0 += acc[nt][0] * av.x + acc[nt][1] * av.y;
        ps0 += acc[nt][0] * bv.x + acc[nt][1] * bv.y;
        pd1 += acc[nt][2] * av.x + acc[nt][3] * av.y;
        ps1 += acc[nt][2] * bv.x + acc[nt][3] * bv.y;
    }
    #pragma unroll
    for (int off = 2; off >= 1; off >>= 1) {
        pd0 += __shfl_xor_sync(0xffffffffu, pd0, off);
        ps0 += __shfl_xor_sync(0xffffffffu, ps0, off);
        pd1 += __shfl_xor_sync(0xffffffffu, pd1, off);
        ps1 += __shfl_xor_sync(0xffffffffu, ps1, off);
    }

    const int row0 = rowbase + warp * 16 + g;
    const int row1 = row0 + 8;
    if (q == 0) {
        if (row0 < NNODES) { sd[row0] = pd0; ss[row0] = ps0; }
        if (row1 < NNODES) { sd[row1] = pd1; ss[row1] = ps1; }
    }
    if (row0 < NNODES) {
        #pragma unroll
        for (int nt = 0; nt < 8; nt++) {
            const __half2 hv = __floats2half2_rn(acc[nt][0], acc[nt][1]);
            *reinterpret_cast<__half2*>(&h[(size_t)row0 * 64 + nt * 8 + 2 * q]) = hv;
        }
    }
    if (row1 < NNODES) {
        #pragma unroll
        for (int nt = 0; nt < 8; nt++) {
            const __half2 hv = __floats2half2_rn(acc[nt][2], acc[nt][3]);
            *reinterpret_cast<__half2*>(&h[(size_t)row1 * 64 + nt * 8 + 2 * q]) = hv;
        }
    }
}

// ---------------------------------------------------------------------------
// Attention softmax (K=16) + fp16 gather + bias + relu.  TWO nodes per warp;
// lane owns 4 feature cols (uint2). Gather loop unrolled by 4 with explicit
// load batching -> MLP=4 (needs >32 regs; launch_bounds relaxed to 6 blocks).
// ---------------------------------------------------------------------------
__global__ void __launch_bounds__(256, 6) agg_kernel(
    const uint2* __restrict__ hh, const int* __restrict__ ecol,
    const float* __restrict__ sd, const float* __restrict__ ss,
    const float* __restrict__ b, float4* __restrict__ out)
{
    const int warp = (blockIdx.x * blockDim.x + threadIdx.x) >> 5;
    const int lane = threadIdx.x & 31;
    const int l16  = lane & 15;
    const int node = warp * 2 + (lane >> 4);

    const int col = ecol[warp * 32 + lane];   // coalesced

    float ev = sd[node] + ss[col];
    ev = (ev > 0.0f) ? ev : 0.2f * ev;        // leaky_relu slope 0.2

    float m = ev;
    #pragma unroll
    for (int off = 8; off >= 1; off >>= 1)
        m = fmaxf(m, __shfl_xor_sync(0xffffffffu, m, off));
    const float ex = __expf(ev - m);
    float s = ex;
    #pragma unroll
    for (int off = 8; off >= 1; off >>= 1)
        s += __shfl_xor_sync(0xffffffffu, s, off);
    const float att = ex / s;

    unsigned long long accA = 0ull, accB = 0ull;   // f32x2 accumulators
    #pragma unroll
    for (int k0 = 0; k0 < KNB; k0 += 4) {
        // broadcast the 4 neighbor ids first, then issue 4 independent LDG.64s
        const int c0 = __shfl_sync(0xffffffffu, col, k0 + 0, 16);
        const int c1 = __shfl_sync(0xffffffffu, col, k0 + 1, 16);
        const int c2 = __shfl_sync(0xffffffffu, col, k0 + 2, 16);
        const int c3 = __shfl_sync(0xffffffffu, col, k0 + 3, 16);
        const uint2 v0 = hh[(size_t)c0 * 16 + l16];
        const uint2 v1 = hh[(size_t)c1 * 16 + l16];
        const uint2 v2 = hh[(size_t)c2 * 16 + l16];
        const uint2 v3 = hh[(size_t)c3 * 16 + l16];
        const float a0 = __shfl_sync(0xffffffffu, att, k0 + 0, 16);
        const float a1 = __shfl_sync(0xffffffffu, att, k0 + 1, 16);
        const float a2 = __shfl_sync(0xffffffffu, att, k0 + 2, 16);
        const float a3 = __shfl_sync(0xffffffffu, att, k0 + 3, 16);

        {
            const float2 lo = __half22float2(*reinterpret_cast<const __half2*>(&v0.x));
            const float2 hi = __half22float2(*reinterpret_cast<const __half2*>(&v0.y));
            const unsigned long long pa = pack2(a0);
            ffma2(accA, pa, pack2s(lo.x, lo.y));
            ffma2(accB, pa, pack2s(hi.x, hi.y));
        }
        {
            const float2 lo = __half22float2(*reinterpret_cast<const __half2*>(&v1.x));
            const float2 hi = __half22float2(*reinterpret_cast<const __half2*>(&v1.y));
            const unsigned long long pa = pack2(a1);
            ffma2(accA, pa, pack2s(lo.x, lo.y));
            ffma2(accB, pa, pack2s(hi.x, hi.y));
        }
        {
            const float2 lo = __half22float2(*reinterpret_cast<const __half2*>(&v2.x));
            const float2 hi = __half22float2(*reinterpret_cast<const __half2*>(&v2.y));
            const unsigned long long pa = pack2(a2);
            ffma2(accA, pa, pack2s(lo.x, lo.y));
            ffma2(accB, pa, pack2s(hi.x, hi.y));
        }
        {
            const float2 lo = __half22float2(*reinterpret_cast<const __half2*>(&v3.x));
            const float2 hi = __half22float2(*reinterpret_cast<const __half2*>(&v3.y));
            const unsigned long long pa = pack2(a3);
            ffma2(accA, pa, pack2s(lo.x, lo.y));
            ffma2(accB, pa, pack2s(hi.x, hi.y));
        }
    }

    const float2 rA = unpack2(accA);
    const float2 rB = unpack2(accB);
    const float4 bv = reinterpret_cast<const float4*>(b)[l16];
    float4 o;
    o.x = fmaxf(rA.x + bv.x, 0.0f);
    o.y = fmaxf(rA.y + bv.y, 0.0f);
    o.z = fmaxf(rB.x + bv.z, 0.0f);
    o.w = fmaxf(rB.y + bv.w, 0.0f);
    out[(size_t)node * 16 + l16] = o;
}

// ---------------------------------------------------------------------------
extern "C" void kernel_launch(void* const* d_in, const int* in_sizes, int n_in,
                              void* d_out, int out_size)
{
    const float* x    = (const float*)d_in[0];
    // d_in[1] = edge_row: exactly K per node, row-sorted -> implicit, unused
    const int*   ecol = (const int*)d_in[2];
    const float* W1   = (const float*)d_in[3];
    const float* a1   = (const float*)d_in[4];
    const float* b1   = (const float*)d_in[5];
    const float* W2   = (const float*)d_in[6];
    const float* a2   = (const float*)d_in[7];
    const float* b2   = (const float*)d_in[8];

    __half* h;  float *x1, *sd, *ss;
    cudaGetSymbolAddress((void**)&h,  g_h);
    cudaGetSymbolAddress((void**)&x1, g_x1);
    cudaGetSymbolAddress((void**)&sd, g_sd);
    cudaGetSymbolAddress((void**)&ss, g_ss);

    const int smem1 = (128 * 72 + 128 * 132) * 4;   // ~102 KB
    const int smem2 = (64 * 72 + 128 * 68) * 4;     // ~52 KB
    cudaFuncSetAttribute(gemm_mma_kernel<128>,
                         cudaFuncAttributeMaxDynamicSharedMemorySize, smem1);
    cudaFuncSetAttribute(gemm_mma_kernel<64>,
                         cudaFuncAttributeMaxDynamicSharedMemorySize, smem2);

    const int gemm_blocks = (NNODES + 127) / 128;   // 782
    const int agg_blocks  = NNODES / 16;            // 6250 (8 warps x 2 nodes)

    // Layer 1
    gemm_mma_kernel<128><<<gemm_blocks, 256, smem1>>>(x, W1, a1, h, sd, ss);
    agg_kernel<<<agg_blocks, 256>>>((const uint2*)h, ecol, sd, ss, b1,
                                    (float4*)x1);
    // Layer 2
    gemm_mma_kernel<64><<<gemm_blocks, 256, smem2>>>(x1, W2, a2, h, sd, ss);
    agg_kernel<<<agg_blocks, 256>>>((const uint2*)h, ecol, sd, ss, b2,
                                    (float4*)d_out);
}

// round 11
// speedup vs baseline: 1.0317x; 1.0317x over previous
#include <cuda_runtime.h>
#include <cuda_fp16.h>
#include <math.h>

#define NNODES 100000
#define KNB 16

// Scratch (bss, no allocation). h reused by both layers (sequential stream).
__device__ __align__(16) __half g_h[NNODES * 64];
__device__ __align__(16) float  g_x1[NNODES * 64];
__device__ float g_sd[NNODES];
__device__ float g_ss[NNODES];

// ---- helpers ---------------------------------------------------------------
__device__ __forceinline__ unsigned cvt_tf32(float f) {
    unsigned u;
    asm("cvt.rna.tf32.f32 %0, %1;" : "=r"(u) : "f"(f));
    return u;
}
__device__ __forceinline__ void mma_tf32(float* c,
    unsigned a0, unsigned a1, unsigned a2, unsigned a3,
    unsigned b0, unsigned b1)
{
    asm volatile(
        "mma.sync.aligned.m16n8k8.row.col.f32.tf32.tf32.f32 "
        "{%0,%1,%2,%3}, {%4,%5,%6,%7}, {%8,%9}, {%0,%1,%2,%3};"
        : "+f"(c[0]), "+f"(c[1]), "+f"(c[2]), "+f"(c[3])
        : "r"(a0), "r"(a1), "r"(a2), "r"(a3), "r"(b0), "r"(b1));
}
__device__ __forceinline__ unsigned smem_u32(const void* p) {
    unsigned a;
    asm("{ .reg .u64 t; cvta.to.shared.u64 t, %1; cvt.u32.u64 %0, t; }"
        : "=r"(a) : "l"(p));
    return a;
}
__device__ __forceinline__ void cp_async16(unsigned dst, const void* src, int sz) {
    asm volatile("cp.async.ca.shared.global [%0], [%1], 16, %2;"
                 :: "r"(dst), "l"(src), "r"(sz));
}

// ---------------------------------------------------------------------------
// GEMM h = x @ W (KD inner, 64 cols) on tf32 tensor cores + fused attention
// dots sd[i]=h[i].a[0:64], ss[i]=h[i].a[64:128]; h stored fp16.
// x tile cp.async'd as RAW fp32 bits (tensor core truncates to tf32); the
// -3.52e-4 truncation bias is cancelled by scaling W (rna) at fill time.
// NEW: x fill split into 2 commit groups along k; first half of the MMA
// mainloop runs under wait_group 1 while the second half streams in.
// ---------------------------------------------------------------------------
template <int KD>
__global__ void __launch_bounds__(256) gemm_mma_kernel(
    const float* __restrict__ x, const float* __restrict__ W,
    const float* __restrict__ a, __half* __restrict__ h,
    float* __restrict__ sd, float* __restrict__ ss)
{
    constexpr int XS = KD + 4;    // padded x row stride (u32 units)
    constexpr int WS = 72;        // padded W row stride (u32 units)
    constexpr int K4 = KD / 4;    // 16B chunks per x row
    constexpr int K4H = K4 / 2;   // chunks per stage
    extern __shared__ unsigned smem_u[];
    unsigned* Wsu = smem_u;               // KD x WS   (tf32-rna, bias-comp)
    unsigned* xsu = smem_u + KD * WS;     // 128 x XS  (raw fp32 bits)

    const int tid  = threadIdx.x;
    const int warp = tid >> 5;
    const int lane = tid & 31;
    const int q = lane & 3;
    const int g = lane >> 2;
    const int rowbase = blockIdx.x * 128;

    const float4* xg = reinterpret_cast<const float4*>(x + (size_t)rowbase * KD);
    const unsigned xsa = smem_u32(xsu);
    const int nvr = NNODES - rowbase;     // valid rows in this tile (may be <128)

    // Stage 0: k-chunks [0, K4H)
    #pragma unroll 4
    for (int i = tid; i < 128 * K4H; i += 256) {
        const int r = i / K4H, c = i % K4H;
        const unsigned dst = xsa + (unsigned)(r * XS + c * 4) * 4u;
        const int sz = (r < nvr) ? 16 : 0;
        cp_async16(dst, xg + (sz ? (r * K4 + c) : 0), sz);
    }
    asm volatile("cp.async.commit_group;");
    // Stage 1: k-chunks [K4H, K4)
    #pragma unroll 4
    for (int i = tid; i < 128 * K4H; i += 256) {
        const int r = i / K4H, c = K4H + i % K4H;
        const unsigned dst = xsa + (unsigned)(r * XS + c * 4) * 4u;
        const int sz = (r < nvr) ? 16 : 0;
        cp_async16(dst, xg + (sz ? (r * K4 + c) : 0), sz);
    }
    asm volatile("cp.async.commit_group;");

    // W tile: rna cvt + truncation-bias compensation (tiny: KD*64 elements)
    {
        const float comp = 1.000352f;
        const float4* Wg = reinterpret_cast<const float4*>(W);
        #pragma unroll
        for (int i = tid; i < KD * 16; i += 256) {
            const float4 v = Wg[i];
            const int k = i >> 4, n4 = i & 15;
            uint4 u;
            u.x = cvt_tf32(v.x * comp); u.y = cvt_tf32(v.y * comp);
            u.z = cvt_tf32(v.z * comp); u.w = cvt_tf32(v.w * comp);
            *reinterpret_cast<uint4*>(&Wsu[k * WS + n4 * 4]) = u;
        }
    }

    float acc[8][4];
    #pragma unroll
    for (int nt = 0; nt < 8; nt++)
        #pragma unroll
        for (int j = 0; j < 4; j++) acc[nt][j] = 0.0f;

    const unsigned* xw = &xsu[(warp * 16) * XS];

    // First half of k under stage-0 data
    asm volatile("cp.async.wait_group 1;");
    __syncthreads();
    #pragma unroll
    for (int k0 = 0; k0 < KD / 2; k0 += 8) {
        const unsigned a0 = xw[g * XS + k0 + q];
        const unsigned a1 = xw[(g + 8) * XS + k0 + q];
        const unsigned a2 = xw[g * XS + k0 + q + 4];
        const unsigned a3 = xw[(g + 8) * XS + k0 + q + 4];
        #pragma unroll
        for (int nt = 0; nt < 8; nt++) {
            const unsigned b0 = Wsu[(k0 + q) * WS + nt * 8 + g];
            const unsigned b1 = Wsu[(k0 + q + 4) * WS + nt * 8 + g];
            mma_tf32(acc[nt], a0, a1, a2, a3, b0, b1);
        }
    }
    // Second half
    asm volatile("cp.async.wait_group 0;");
    __syncthreads();
    #pragma unroll
    for (int k0 = KD / 2; k0 < KD; k0 += 8) {
        const unsigned a0 = xw[g * XS + k0 + q];
        const unsigned a1 = xw[(g + 8) * XS + k0 + q];
        const unsigned a2 = xw[g * XS + k0 + q + 4];
        const unsigned a3 = xw[(g + 8) * XS + k0 + q + 4];
        #pragma unroll
        for (int nt = 0; nt < 8; nt++) {
            const unsigned b0 = Wsu[(k0 + q) * WS + nt * 8 + g];
            const unsigned b1 = Wsu[(k0 + q + 4) * WS + nt * 8 + g];
            mma_tf32(acc[nt], a0, a1, a2, a3, b0, b1);
        }
    }

    // Fused attention dots. Thread owns rows (16w+g, 16w+g+8), cols {8nt+2q,+1}.
    float pd0 = 0.f, ps0 = 0.f, pd1 = 0.f, ps1 = 0.f;
    #pragma unroll
    for (int nt = 0; nt < 8; nt++) {
        const float2 av = reinterpret_cast<const float2*>(a)[nt * 4 + q];
        const float2 bv = reinterpret_cast<const float2*>(a + 64)[nt * 4 + q];
        pd0 += acc[nt][0] * av.x + acc[nt][1] * av.y;
        ps0 += acc[nt][0] * bv.x + acc[nt][1] * bv.y;
        pd1 += acc[nt][2] * av.x + acc[nt][3] * av.y;
        ps1 += acc[nt][2] * bv.x + acc[nt][3] * bv.y;
    }
    #pragma unroll
    for (int off = 2; off >= 1; off >>= 1) {
        pd0 += __shfl_xor_sync(0xffffffffu, pd0, off);
        ps0 += __shfl_xor_sync(0xffffffffu, ps0, off);
        pd1 += __shfl_xor_sync(0xffffffffu, pd1, off);
        ps1 += __shfl_xor_sync(0xffffffffu, ps1, off);
    }

    const int row0 = rowbase + warp * 16 + g;
    const int row1 = row0 + 8;
    if (q == 0) {
        if (row0 < NNODES) { sd[row0] = pd0; ss[row0] = ps0; }
        if (row1 < NNODES) { sd[row1] = pd1; ss[row1] = ps1; }
    }
    if (row0 < NNODES) {
        #pragma unroll
        for (int nt = 0; nt < 8; nt++) {
            const __half2 hv = __floats2half2_rn(acc[nt][0], acc[nt][1]);
            *reinterpret_cast<__half2*>(&h[(size_t)row0 * 64 + nt * 8 + 2 * q]) = hv;
        }
    }
    if (row1 < NNODES) {
        #pragma unroll
        for (int nt = 0; nt < 8; nt++) {
            const __half2 hv = __floats2half2_rn(acc[nt][2], acc[nt][3]);
            *reinterpret_cast<__half2*>(&h[(size_t)row1 * 64 + nt * 8 + 2 * q]) = hv;
        }
    }
}

// ---------------------------------------------------------------------------
// Attention softmax (K=16) + fp16 gather + bias + relu.  TWO nodes per warp;
// lane owns 4 feature cols (uint2 = 2 half2). fp16 HFMA2 accumulation: att is
// pre-packed into a replicated half2 per lane BEFORE the loop, and the loop
// shuffles the packed bits -> per k: 2 SHFL + 1 LDG.64 + 2 HFMA2, no cvt.
// ---------------------------------------------------------------------------
__global__ void __launch_bounds__(256) agg_kernel(
    const uint2* __restrict__ hh, const int* __restrict__ ecol,
    const float* __restrict__ sd, const float* __restrict__ ss,
    const float* __restrict__ b, float4* __restrict__ out)
{
    const int warp = (blockIdx.x * blockDim.x + threadIdx.x) >> 5;
    const int lane = threadIdx.x & 31;
    const int l16  = lane & 15;
    const int node = warp * 2 + (lane >> 4);

    const int col = ecol[warp * 32 + lane];   // coalesced

    float ev = sd[node] + ss[col];
    ev = (ev > 0.0f) ? ev : 0.2f * ev;        // leaky_relu slope 0.2

    float m = ev;
    #pragma unroll
    for (int off = 8; off >= 1; off >>= 1)
        m = fmaxf(m, __shfl_xor_sync(0xffffffffu, m, off));
    const float ex = __expf(ev - m);
    float s = ex;
    #pragma unroll
    for (int off = 8; off >= 1; off >>= 1)
        s += __shfl_xor_sync(0xffffffffu, s, off);
    const float att = ex / s;

    // pre-pack this lane's attention weight as {att, att} in half2 bits
    const __half2 hatt = __float2half2_rn(att);
    const unsigned hatt_u = *reinterpret_cast<const unsigned*>(&hatt);

    __half2 accA = __float2half2_rn(0.0f);
    __half2 accB = accA;
    #pragma unroll
    for (int k = 0; k < KNB; k++) {
        const int      ck = __shfl_sync(0xffffffffu, col, k, 16);
        const unsigned au = __shfl_sync(0xffffffffu, hatt_u, k, 16);
        const uint2    hv = hh[(size_t)ck * 16 + l16];
        const __half2  pa = *reinterpret_cast<const __half2*>(&au);
        accA = __hfma2(pa, *reinterpret_cast<const __half2*>(&hv.x), accA);
        accB = __hfma2(pa, *reinterpret_cast<const __half2*>(&hv.y), accB);
    }

    const float2 rA = __half22float2(accA);
    const float2 rB = __half22float2(accB);
    const float4 bv = reinterpret_cast<const float4*>(b)[l16];
    float4 o;
    o.x = fmaxf(rA.x + bv.x, 0.0f);
    o.y = fmaxf(rA.y + bv.y, 0.0f);
    o.z = fmaxf(rB.x + bv.z, 0.0f);
    o.w = fmaxf(rB.y + bv.w, 0.0f);
    out[(size_t)node * 16 + l16] = o;
}

// ---------------------------------------------------------------------------
extern "C" void kernel_launch(void* const* d_in, const int* in_sizes, int n_in,
                              void* d_out, int out_size)
{
    const float* x    = (const float*)d_in[0];
    // d_in[1] = edge_row: exactly K per node, row-sorted -> implicit, unused
    const int*   ecol = (const int*)d_in[2];
    const float* W1   = (const float*)d_in[3];
    const float* a1   = (const float*)d_in[4];
    const float* b1   = (const float*)d_in[5];
    const float* W2   = (const float*)d_in[6];
    const float* a2   = (const float*)d_in[7];
    const float* b2   = (const float*)d_in[8];

    __half* h;  float *x1, *sd, *ss;
    cudaGetSymbolAddress((void**)&h,  g_h);
    cudaGetSymbolAddress((void**)&x1, g_x1);
    cudaGetSymbolAddress((void**)&sd, g_sd);
    cudaGetSymbolAddress((void**)&ss, g_ss);

    const int smem1 = (128 * 72 + 128 * 132) * 4;   // ~102 KB
    const int smem2 = (64 * 72 + 128 * 68) * 4;     // ~52 KB
    cudaFuncSetAttribute(gemm_mma_kernel<128>,
                         cudaFuncAttributeMaxDynamicSharedMemorySize, smem1);
    cudaFuncSetAttribute(gemm_mma_kernel<64>,
                         cudaFuncAttributeMaxDynamicSharedMemorySize, smem2);

    const int gemm_blocks = (NNODES + 127) / 128;   // 782
    const int agg_blocks  = NNODES / 16;            // 6250 (8 warps x 2 nodes)

    // Layer 1
    gemm_mma_kernel<128><<<gemm_blocks, 256, smem1>>>(x, W1, a1, h, sd, ss);
    agg_kernel<<<agg_blocks, 256>>>((const uint2*)h, ecol, sd, ss, b1,
                                    (float4*)x1);
    // Layer 2
    gemm_mma_kernel<64><<<gemm_blocks, 256, smem2>>>(x1, W2, a2, h, sd, ss);
    agg_kernel<<<agg_blocks, 256>>>((const uint2*)h, ecol, sd, ss, b2,
                                    (float4*)d_out);
}

// round 14
// speedup vs baseline: 1.0324x; 1.0007x over previous
#include <cuda_runtime.h>
#include <cuda_fp16.h>
#include <math.h>

#define NNODES 100000
#define KNB 16

// Scratch (bss, no allocation). h reused by both layers (sequential stream).
__device__ __align__(16) __half g_h[NNODES * 64];
__device__ __align__(16) float  g_x1[NNODES * 64];
__device__ float g_sd[NNODES];
__device__ float g_ss[NNODES];

// ---- helpers ---------------------------------------------------------------
__device__ __forceinline__ unsigned cvt_tf32(float f) {
    unsigned u;
    asm("cvt.rna.tf32.f32 %0, %1;" : "=r"(u) : "f"(f));
    return u;
}
__device__ __forceinline__ void mma_tf32(float* c,
    unsigned a0, unsigned a1, unsigned a2, unsigned a3,
    unsigned b0, unsigned b1)
{
    asm volatile(
        "mma.sync.aligned.m16n8k8.row.col.f32.tf32.tf32.f32 "
        "{%0,%1,%2,%3}, {%4,%5,%6,%7}, {%8,%9}, {%0,%1,%2,%3};"
        : "+f"(c[0]), "+f"(c[1]), "+f"(c[2]), "+f"(c[3])
        : "r"(a0), "r"(a1), "r"(a2), "r"(a3), "r"(b0), "r"(b1));
}
__device__ __forceinline__ unsigned smem_u32(const void* p) {
    unsigned a;
    asm("{ .reg .u64 t; cvta.to.shared.u64 t, %1; cvt.u32.u64 %0, t; }"
        : "=r"(a) : "l"(p));
    return a;
}
__device__ __forceinline__ void cp_async16(unsigned dst, const void* src, int sz) {
    asm volatile("cp.async.ca.shared.global [%0], [%1], 16, %2;"
                 :: "r"(dst), "l"(src), "r"(sz));
}

// ---------------------------------------------------------------------------
// GEMM h = x @ W (KD inner, 64 cols) on tf32 tensor cores + fused attention
// dots sd[i]=h[i].a[0:64], ss[i]=h[i].a[64:128]; h stored fp16.
// x tile cp.async'd as RAW fp32 bits (tensor core truncates to tf32); the
// -3.52e-4 truncation bias is cancelled by scaling W (rna) at fill time.
// x fill split into 2 commit groups along k; first half of the MMA mainloop
// runs under wait_group 1 while the second half streams in.
// ---------------------------------------------------------------------------
template <int KD>
__global__ void __launch_bounds__(256) gemm_mma_kernel(
    const float* __restrict__ x, const float* __restrict__ W,
    const float* __restrict__ a, __half* __restrict__ h,
    float* __restrict__ sd, float* __restrict__ ss)
{
    constexpr int XS = KD + 4;    // padded x row stride (u32 units)
    constexpr int WS = 72;        // padded W row stride (u32 units)
    constexpr int K4 = KD / 4;    // 16B chunks per x row
    constexpr int K4H = K4 / 2;   // chunks per stage
    extern __shared__ unsigned smem_u[];
    unsigned* Wsu = smem_u;               // KD x WS   (tf32-rna, bias-comp)
    unsigned* xsu = smem_u + KD * WS;     // 128 x XS  (raw fp32 bits)

    const int tid  = threadIdx.x;
    const int warp = tid >> 5;
    const int lane = tid & 31;
    const int q = lane & 3;
    const int g = lane >> 2;
    const int rowbase = blockIdx.x * 128;

    const float4* xg = reinterpret_cast<const float4*>(x + (size_t)rowbase * KD);
    const unsigned xsa = smem_u32(xsu);
    const int nvr = NNODES - rowbase;

    // Stage 0: k-chunks [0, K4H)
    #pragma unroll 4
    for (int i = tid; i < 128 * K4H; i += 256) {
        const int r = i / K4H, c = i % K4H;
        const unsigned dst = xsa + (unsigned)(r * XS + c * 4) * 4u;
        const int sz = (r < nvr) ? 16 : 0;
        cp_async16(dst, xg + (sz ? (r * K4 + c) : 0), sz);
    }
    asm volatile("cp.async.commit_group;");
    // Stage 1: k-chunks [K4H, K4)
    #pragma unroll 4
    for (int i = tid; i < 128 * K4H; i += 256) {
        const int r = i / K4H, c = K4H + i % K4H;
        const unsigned dst = xsa + (unsigned)(r * XS + c * 4) * 4u;
        const int sz = (r < nvr) ? 16 : 0;
        cp_async16(dst, xg + (sz ? (r * K4 + c) : 0), sz);
    }
    asm volatile("cp.async.commit_group;");

    // W tile: rna cvt + truncation-bias compensation (tiny: KD*64 elements)
    {
        const float comp = 1.000352f;
        const float4* Wg = reinterpret_cast<const float4*>(W);
        #pragma unroll
        for (int i = tid; i < KD * 16; i += 256) {
            const float4 v = Wg[i];
            const int k = i >> 4, n4 = i & 15;
            uint4 u;
            u.x = cvt_tf32(v.x * comp); u.y = cvt_tf32(v.y * comp);
            u.z = cvt_tf32(v.z * comp); u.w = cvt_tf32(v.w * comp);
            *reinterpret_cast<uint4*>(&Wsu[k * WS + n4 * 4]) = u;
        }
    }

    float acc[8][4];
    #pragma unroll
    for (int nt = 0; nt < 8; nt++)
        #pragma unroll
        for (int j = 0; j < 4; j++) acc[nt][j] = 0.0f;

    const unsigned* xw = &xsu[(warp * 16) * XS];

    asm volatile("cp.async.wait_group 1;");
    __syncthreads();
    #pragma unroll
    for (int k0 = 0; k0 < KD / 2; k0 += 8) {
        const unsigned a0 = xw[g * XS + k0 + q];
        const unsigned a1 = xw[(g + 8) * XS + k0 + q];
        const unsigned a2 = xw[g * XS + k0 + q + 4];
        const unsigned a3 = xw[(g + 8) * XS + k0 + q + 4];
        #pragma unroll
        for (int nt = 0; nt < 8; nt++) {
            const unsigned b0 = Wsu[(k0 + q) * WS + nt * 8 + g];
            const unsigned b1 = Wsu[(k0 + q + 4) * WS + nt * 8 + g];
            mma_tf32(acc[nt], a0, a1, a2, a3, b0, b1);
        }
    }
    asm volatile("cp.async.wait_group 0;");
    __syncthreads();
    #pragma unroll
    for (int k0 = KD / 2; k0 < KD; k0 += 8) {
        const unsigned a0 = xw[g * XS + k0 + q];
        const unsigned a1 = xw[(g + 8) * XS + k0 + q];
        const unsigned a2 = xw[g * XS + k0 + q + 4];
        const unsigned a3 = xw[(g + 8) * XS + k0 + q + 4];
        #pragma unroll
        for (int nt = 0; nt < 8; nt++) {
            const unsigned b0 = Wsu[(k0 + q) * WS + nt * 8 + g];
            const unsigned b1 = Wsu[(k0 + q + 4) * WS + nt * 8 + g];
            mma_tf32(acc[nt], a0, a1, a2, a3, b0, b1);
        }
    }

    // Fused attention dots. Thread owns rows (16w+g, 16w+g+8), cols {8nt+2q,+1}.
    float pd0 = 0.f, ps0 = 0.f, pd1 = 0.f, ps1 = 0.f;
    #pragma unroll
    for (int nt = 0; nt < 8; nt++) {
        const float2 av = reinterpret_cast<const float2*>(a)[nt * 4 + q];
        const float2 bv = reinterpret_cast<const float2*>(a + 64)[nt * 4 + q];
        pd0 += acc[nt][0] * av.x + acc[nt][1] * av.y;
        ps0 += acc[nt][0] * bv.x + acc[nt][1] * bv.y;
        pd1 += acc[nt][2] * av.x + acc[nt][3] * av.y;
        ps1 += acc[nt][2] * bv.x + acc[nt][3] * bv.y;
    }
    #pragma unroll
    for (int off = 2; off >= 1; off >>= 1) {
        pd0 += __shfl_xor_sync(0xffffffffu, pd0, off);
        ps0 += __shfl_xor_sync(0xffffffffu, ps0, off);
        pd1 += __shfl_xor_sync(0xffffffffu, pd1, off);
        ps1 += __shfl_xor_sync(0xffffffffu, ps1, off);
    }

    const int row0 = rowbase + warp * 16 + g;
    const int row1 = row0 + 8;
    if (q == 0) {
        if (row0 < NNODES) { sd[row0] = pd0; ss[row0] = ps0; }
        if (row1 < NNODES) { sd[row1] = pd1; ss[row1] = ps1; }
    }
    if (row0 < NNODES) {
        #pragma unroll
        for (int nt = 0; nt < 8; nt++) {
            const __half2 hv = __floats2half2_rn(acc[nt][0], acc[nt][1]);
            *reinterpret_cast<__half2*>(&h[(size_t)row0 * 64 + nt * 8 + 2 * q]) = hv;
        }
    }
    if (row1 < NNODES) {
        #pragma unroll
        for (int nt = 0; nt < 8; nt++) {
            const __half2 hv = __floats2half2_rn(acc[nt][2], acc[nt][3]);
            *reinterpret_cast<__half2*>(&h[(size_t)row1 * 64 + nt * 8 + 2 * q]) = hv;
        }
    }
}

// ---------------------------------------------------------------------------
// Attention softmax (K=16) + fp16 gather + bias + relu.  TWO nodes per warp;
// lane owns 4 feature cols (uint2 = 2 half2).
// NEW: after softmax each lane stores (col*16, att-half2) to smem (STS.64);
// gather loop reads TWO pairs per LDS.128 (16-lane broadcast) -> loop MIO ops
// per 2 neighbors: 1 LDS + 2 LDG (was 4 SHFL + 2 LDG).
// ---------------------------------------------------------------------------
__global__ void __launch_bounds__(256) agg_kernel(
    const uint2* __restrict__ hh, const int* __restrict__ ecol,
    const float* __restrict__ sd, const float* __restrict__ ss,
    const float* __restrict__ b, float4* __restrict__ out)
{
    __shared__ uint2 pairs[8][32];    // [warp][2 nodes x 16 (off,att) pairs]

    const int wid  = threadIdx.x >> 5;
    const int warp = (blockIdx.x * blockDim.x + threadIdx.x) >> 5;
    const int lane = threadIdx.x & 31;
    const int l16  = lane & 15;
    const int node = warp * 2 + (lane >> 4);

    const int col = ecol[warp * 32 + lane];   // coalesced

    float ev = sd[node] + ss[col];
    ev = (ev > 0.0f) ? ev : 0.2f * ev;        // leaky_relu slope 0.2

    float m = ev;
    #pragma unroll
    for (int off = 8; off >= 1; off >>= 1)
        m = fmaxf(m, __shfl_xor_sync(0xffffffffu, m, off));
    const float ex = __expf(ev - m);
    float s = ex;
    #pragma unroll
    for (int off = 8; off >= 1; off >>= 1)
        s += __shfl_xor_sync(0xffffffffu, s, off);
    const float att = ex / s;

    // publish (uint2-element offset, replicated half2 att) for this edge
    const __half2 hatt = __float2half2_rn(att);
    pairs[wid][lane] = make_uint2((unsigned)col * 16u,
                                  *reinterpret_cast<const unsigned*>(&hatt));
    __syncwarp();

    const uint4* pbase = reinterpret_cast<const uint4*>(&pairs[wid][(lane >> 4) * 16]);

    __half2 accA = __float2half2_rn(0.0f);
    __half2 accB = accA;
    #pragma unroll
    for (int k2 = 0; k2 < KNB / 2; k2++) {
        const uint4 p = pbase[k2];            // LDS.128 broadcast: 2 pairs
        const uint2 v0 = hh[p.x + l16];
        const uint2 v1 = hh[p.z + l16];
        const __half2 a0 = *reinterpret_cast<const __half2*>(&p.y);
        const __half2 a1 = *reinterpret_cast<const __half2*>(&p.w);
        accA = __hfma2(a0, *reinterpret_cast<const __half2*>(&v0.x), accA);
        accB = __hfma2(a0, *reinterpret_cast<const __half2*>(&v0.y), accB);
        accA = __hfma2(a1, *reinterpret_cast<const __half2*>(&v1.x), accA);
        accB = __hfma2(a1, *reinterpret_cast<const __half2*>(&v1.y), accB);
    }

    const float2 rA = __half22float2(accA);
    const float2 rB = __half22float2(accB);
    const float4 bv = reinterpret_cast<const float4*>(b)[l16];
    float4 o;
    o.x = fmaxf(rA.x + bv.x, 0.0f);
    o.y = fmaxf(rA.y + bv.y, 0.0f);
    o.z = fmaxf(rB.x + bv.z, 0.0f);
    o.w = fmaxf(rB.y + bv.w, 0.0f);
    out[(size_t)node * 16 + l16] = o;
}

// ---------------------------------------------------------------------------
extern "C" void kernel_launch(void* const* d_in, const int* in_sizes, int n_in,
                              void* d_out, int out_size)
{
    const float* x    = (const float*)d_in[0];
    // d_in[1] = edge_row: exactly K per node, row-sorted -> implicit, unused
    const int*   ecol = (const int*)d_in[2];
    const float* W1   = (const float*)d_in[3];
    const float* a1   = (const float*)d_in[4];
    const float* b1   = (const float*)d_in[5];
    const float* W2   = (const float*)d_in[6];
    const float* a2   = (const float*)d_in[7];
    const float* b2   = (const float*)d_in[8];

    __half* h;  float *x1, *sd, *ss;
    cudaGetSymbolAddress((void**)&h,  g_h);
    cudaGetSymbolAddress((void**)&x1, g_x1);
    cudaGetSymbolAddress((void**)&sd, g_sd);
    cudaGetSymbolAddress((void**)&ss, g_ss);

    const int smem1 = (128 * 72 + 128 * 132) * 4;   // ~102 KB
    const int smem2 = (64 * 72 + 128 * 68) * 4;     // ~52 KB
    cudaFuncSetAttribute(gemm_mma_kernel<128>,
                         cudaFuncAttributeMaxDynamicSharedMemorySize, smem1);
    cudaFuncSetAttribute(gemm_mma_kernel<64>,
                         cudaFuncAttributeMaxDynamicSharedMemorySize, smem2);

    const int gemm_blocks = (NNODES + 127) / 128;   // 782
    const int agg_blocks  = NNODES / 16;            // 6250 (8 warps x 2 nodes)

    // Layer 1
    gemm_mma_kernel<128><<<gemm_blocks, 256, smem1>>>(x, W1, a1, h, sd, ss);
    agg_kernel<<<agg_blocks, 256>>>((const uint2*)h, ecol, sd, ss, b1,
                                    (float4*)x1);
    // Layer 2
    gemm_mma_kernel<64><<<gemm_blocks, 256, smem2>>>(x1, W2, a2, h, sd, ss);
    agg_kernel<<<agg_blocks, 256>>>((const uint2*)h, ecol, sd, ss, b2,
                                    (float4*)d_out);
}